// round 16
// baseline (speedup 1.0000x reference)
#include <cuda_runtime.h>
#include <cuda_fp16.h>
#include <cstdint>

#define BB 2
#define NN 2048
#define EE 256
#define HH 4
#define DK 64
#define QM 128     // q rows per CTA (flash)
#define BN 64      // keys per tile (flash)
#define NT (NN/BN) // 32 tiles

// scratch (no allocations allowed anywhere)
__device__ __half   g_Qh[BB*HH*NN*DK];    // fp16, pre-scaled by 1/8
__device__ __half   g_Kh[BB*HH*NN*DK];    // fp16, [bh][n][d]
__device__ __half   g_Vt[BB*HH*DK*NN];    // fp16, TRANSPOSED [bh][d][n]
__device__ __half   g_Xhi[BB*NN*EE], g_Xlo[BB*NN*EE];       // x split
__device__ __half   g_Wthi[3*HH*DK*EE], g_Wtlo[3*HH*DK*EE]; // W split, transposed [mat][h][e][d]
__device__ __half   g_Wohi[EE*EE], g_Wolo[EE*EE];           // Wo split [n][k]
__device__ __half   g_Hchi[BB*NN*EE], g_Hclo[BB*NN*EE];     // attention out split
__device__ uint32_t g_adjp[BB*NN*(NN/32)];                  // packed adjacency bits

__device__ __forceinline__ void mma_f16(float* c, const uint32_t* a,
                                        uint32_t b0, uint32_t b1) {
    asm volatile(
        "mma.sync.aligned.m16n8k16.row.col.f32.f16.f16.f32 "
        "{%0,%1,%2,%3}, {%4,%5,%6,%7}, {%8,%9}, {%0,%1,%2,%3};\n"
        : "+f"(c[0]), "+f"(c[1]), "+f"(c[2]), "+f"(c[3])
        : "r"(a[0]), "r"(a[1]), "r"(a[2]), "r"(a[3]), "r"(b0), "r"(b1));
}

__device__ __forceinline__ void hilo_h(float v, __half& hi, __half& lo) {
    hi = __float2half_rn(v);
    lo = __float2half_rn(v - __half2float(hi));
}

__device__ __forceinline__ uint32_t f22h(float a, float b) {
    __half2 h = __floats2half2_rn(a, b);
    return *(uint32_t*)&h;
}

__device__ __forceinline__ uint32_t smem_u32(const void* p) {
    return (uint32_t)__cvta_generic_to_shared(p);
}
__device__ __forceinline__ void cp16(uint32_t dst, const void* src) {
    asm volatile("cp.async.ca.shared.global [%0], [%1], 16;" :: "r"(dst), "l"(src));
}
__device__ __forceinline__ void cp4(uint32_t dst, const void* src) {
    asm volatile("cp.async.ca.shared.global [%0], [%1], 4;" :: "r"(dst), "l"(src));
}
#define CP_COMMIT() asm volatile("cp.async.commit_group;" ::: "memory")
#define CP_WAIT(N)  asm volatile("cp.async.wait_group %0;" :: "n"(N) : "memory")

// ===========================================================================
// Kernel -1: pre-split x / W(transposed) / Wo into fp16 hi/lo planes.
// grid = 4096 x 256 (1M threads; extra tasks for smaller tensors).
// ===========================================================================
__global__ void prep_split_kernel(const float* __restrict__ x,
                                  const float* __restrict__ Wq,
                                  const float* __restrict__ Wk,
                                  const float* __restrict__ Wv,
                                  const float* __restrict__ Wo) {
    const int idx = blockIdx.x * 256 + threadIdx.x;
    {   // x: 1,048,576 elements
        __half hi, lo;
        hilo_h(x[idx], hi, lo);
        g_Xhi[idx] = hi; g_Xlo[idx] = lo;
    }
    if (idx < 3 * HH * EE * DK) {   // 196,608: W[mat][h][d][e] -> Wt[mat][h][e][d]
        const int mat = idx / (HH * EE * DK);
        const int r   = idx % (HH * EE * DK);
        const int h   = r / (EE * DK);
        const int r2  = r % (EE * DK);
        const int e   = r2 / EE;    // dest row (output feature)
        const int d   = r2 % EE;    // dest col (input feature) -> coalesced writes
        const float* W = (mat == 0) ? Wq : (mat == 1 ? Wk : Wv);
        __half hi, lo;
        hilo_h(W[(h * EE + d) * DK + e], hi, lo);
        g_Wthi[idx] = hi; g_Wtlo[idx] = lo;   // idx == ((mat*HH+h)*DK+e)*EE + d
    }
    if (idx < EE * EE) {            // 65,536: Wo stays [n][k]
        __half hi, lo;
        hilo_h(Wo[idx], hi, lo);
        g_Wohi[idx] = hi; g_Wolo[idx] = lo;
    }
}

// ===========================================================================
// Kernel 0: pack adjacency to bitmask.
// ===========================================================================
__global__ void pack_adj_kernel(const int* __restrict__ adj) {
    const int lane = threadIdx.x & 31;
    const size_t wbase = (size_t)((blockIdx.x * blockDim.x + threadIdx.x) >> 5) * 32;
    uint32_t mine = 0;
    #pragma unroll
    for (int j = 0; j < 32; j++) {
        int v = adj[(wbase + j) * 32 + lane];
        uint32_t m = __ballot_sync(0xffffffffu, v != 0);
        if (j == lane) mine = m;
    }
    g_adjp[wbase + lane] = mine;
}

// ===========================================================================
// Kernel 1: QKV projection, raw-copy staging from pre-split planes.
// grid = (64, 12), 128 threads.
// ===========================================================================
__global__ void __launch_bounds__(128) qkv_mma_kernel() {
    __shared__ __half Xhi[64][40], Xlo[64][40];
    __shared__ __half Whi[64][40], Wlo[64][40];   // [e][k]
    __shared__ __half Vsm[64 * 72];               // V transpose buffer [d][n]

    const int mat = blockIdx.y >> 2;
    const int h   = blockIdx.y & 3;
    const int m0  = blockIdx.x * 64;
    const int tid = threadIdx.x;
    const int wid = tid >> 5;
    const int lane = tid & 31;
    const int g = lane >> 2, t = lane & 3;
    const int row0 = wid * 16 + g, row1 = row0 + 8;

    const int xr = tid >> 1, xq = tid & 1;
    const __half* Xsrc_hi = g_Xhi + (size_t)(m0 + xr) * EE + xq * 16;
    const __half* Xsrc_lo = g_Xlo + (size_t)(m0 + xr) * EE + xq * 16;
    const __half* Wsrc_hi = g_Wthi + ((size_t)(mat * HH + h) * DK + xr) * EE + xq * 16;
    const __half* Wsrc_lo = g_Wtlo + ((size_t)(mat * HH + h) * DK + xr) * EE + xq * 16;

    float c[8][4] = {};

    for (int k0 = 0; k0 < EE; k0 += 32) {
        *(uint4*)(&Xhi[xr][xq * 16])     = *(const uint4*)(Xsrc_hi + k0);
        *(uint4*)(&Xhi[xr][xq * 16 + 8]) = *(const uint4*)(Xsrc_hi + k0 + 8);
        *(uint4*)(&Xlo[xr][xq * 16])     = *(const uint4*)(Xsrc_lo + k0);
        *(uint4*)(&Xlo[xr][xq * 16 + 8]) = *(const uint4*)(Xsrc_lo + k0 + 8);
        *(uint4*)(&Whi[xr][xq * 16])     = *(const uint4*)(Wsrc_hi + k0);
        *(uint4*)(&Whi[xr][xq * 16 + 8]) = *(const uint4*)(Wsrc_hi + k0 + 8);
        *(uint4*)(&Wlo[xr][xq * 16])     = *(const uint4*)(Wsrc_lo + k0);
        *(uint4*)(&Wlo[xr][xq * 16 + 8]) = *(const uint4*)(Wsrc_lo + k0 + 8);
        __syncthreads();

        #pragma unroll
        for (int kc = 0; kc < 32; kc += 16) {
            uint32_t ahi[4], alo[4];
            ahi[0] = *(const uint32_t*)(&Xhi[row0][kc + 2 * t]);
            ahi[1] = *(const uint32_t*)(&Xhi[row1][kc + 2 * t]);
            ahi[2] = *(const uint32_t*)(&Xhi[row0][kc + 8 + 2 * t]);
            ahi[3] = *(const uint32_t*)(&Xhi[row1][kc + 8 + 2 * t]);
            alo[0] = *(const uint32_t*)(&Xlo[row0][kc + 2 * t]);
            alo[1] = *(const uint32_t*)(&Xlo[row1][kc + 2 * t]);
            alo[2] = *(const uint32_t*)(&Xlo[row0][kc + 8 + 2 * t]);
            alo[3] = *(const uint32_t*)(&Xlo[row1][kc + 8 + 2 * t]);
            #pragma unroll
            for (int nf = 0; nf < 8; nf++) {
                uint32_t bh0 = *(const uint32_t*)(&Whi[nf * 8 + g][kc + 2 * t]);
                uint32_t bh1 = *(const uint32_t*)(&Whi[nf * 8 + g][kc + 8 + 2 * t]);
                uint32_t bl0 = *(const uint32_t*)(&Wlo[nf * 8 + g][kc + 2 * t]);
                uint32_t bl1 = *(const uint32_t*)(&Wlo[nf * 8 + g][kc + 8 + 2 * t]);
                mma_f16(c[nf], ahi, bh0, bh1);
                mma_f16(c[nf], ahi, bl0, bl1);
                mma_f16(c[nf], alo, bh0, bh1);
            }
        }
        __syncthreads();
    }

    if (mat < 2) {
        __half* outp = (mat == 0) ? g_Qh : g_Kh;
        const float sc = (mat == 0) ? 0.125f : 1.0f;
        {
            int m = m0 + row0;
            int b = m >> 11, n = m & (NN - 1);
            __half* dst = outp + ((size_t)(b * HH + h) * NN + n) * DK;
            #pragma unroll
            for (int nf = 0; nf < 8; nf++)
                *(__half2*)(dst + nf * 8 + 2 * t) =
                    __floats2half2_rn(c[nf][0] * sc, c[nf][1] * sc);
        }
        {
            int m = m0 + row1;
            int b = m >> 11, n = m & (NN - 1);
            __half* dst = outp + ((size_t)(b * HH + h) * NN + n) * DK;
            #pragma unroll
            for (int nf = 0; nf < 8; nf++)
                *(__half2*)(dst + nf * 8 + 2 * t) =
                    __floats2half2_rn(c[nf][2] * sc, c[nf][3] * sc);
        }
    } else {
        // V: transpose in SMEM, then write coalesced rows of g_Vt[bh][d][n]
        __syncthreads();
        #pragma unroll
        for (int nf = 0; nf < 8; nf++) {
            int d0 = nf * 8 + 2 * t;
            Vsm[(d0    ) * 72 + row0] = __float2half_rn(c[nf][0]);
            Vsm[(d0 + 1) * 72 + row0] = __float2half_rn(c[nf][1]);
            Vsm[(d0    ) * 72 + row1] = __float2half_rn(c[nf][2]);
            Vsm[(d0 + 1) * 72 + row1] = __float2half_rn(c[nf][3]);
        }
        __syncthreads();
        const int b = m0 >> 11, n0 = m0 & (NN - 1);
        const int d = tid >> 1, part = tid & 1;
        __half* dst = g_Vt + ((size_t)(b * HH + h) * DK + d) * NN + n0 + part * 32;
        const __half* src = &Vsm[d * 72 + part * 32];
        #pragma unroll
        for (int i = 0; i < 4; i++)
            *(uint4*)(dst + i * 8) = *(const uint4*)(src + i * 8);
    }
}

// ===========================================================================
// Kernel 2: flash attention, fp16 m16n8k16, TRIPLE-buffered cp.async,
// ONE __syncthreads per tile. grid = (16, 8), 256 threads, dynamic smem.
// ===========================================================================
#define FL_SMEM (2 * (3 * BN * 72) * 2 + 3 * QM * 2 * 4)   // Ks+Vs halves + adj words

__global__ void __launch_bounds__(256) flash_mma_kernel() {
    extern __shared__ __half smf[];
    __half* Ks = smf;                         // [3][BN][72]  key-major
    __half* Vs = smf + 3 * BN * 72;           // [3][BN][72]  d-major (from g_Vt)
    uint32_t* adjm = (uint32_t*)(smf + 6 * BN * 72);  // [3][QM][2]

    const int tid = threadIdx.x;
    const int wid = tid >> 5;
    const int lane = tid & 31;
    const int g = lane >> 2;
    const int t = lane & 3;
    const int bh = blockIdx.y;
    const int b  = bh >> 2;
    const int q0 = blockIdx.x * QM;

    const int row0 = wid * 16 + g;
    const int row1 = row0 + 8;

    // staging roles
    const int krow = tid >> 2, kq = tid & 3;
    const int arow = tid >> 1, ahalf = tid & 1;
    const __half* Kg0 = g_Kh + ((size_t)bh * NN + krow) * DK + kq * 16;
    const __half* Vg0 = g_Vt + ((size_t)bh * DK + krow) * NN + kq * 16;
    const uint32_t* adjp_base = g_adjp + ((size_t)b * NN + q0 + arow) * (NN / 32) + ahalf;

    // preload Q fragments
    uint32_t qa[4][4];
    {
        const __half* Q0 = g_Qh + ((size_t)bh * NN + q0 + row0) * DK;
        const __half* Q1 = g_Qh + ((size_t)bh * NN + q0 + row1) * DK;
        #pragma unroll
        for (int kc = 0; kc < 4; kc++) {
            qa[kc][0] = *(const uint32_t*)(Q0 + kc * 16 + 2 * t);
            qa[kc][1] = *(const uint32_t*)(Q1 + kc * 16 + 2 * t);
            qa[kc][2] = *(const uint32_t*)(Q0 + kc * 16 + 2 * t + 8);
            qa[kc][3] = *(const uint32_t*)(Q1 + kc * 16 + 2 * t + 8);
        }
    }

    float oacc[8][4] = {};
    float m0r = -1e30f, m1r = -1e30f, l0r = 0.f, l1r = 0.f;

    // prefetch helper (macro to keep addresses simple)
    #define PREFETCH(tt, bb) do { \
        const __half* Kg_ = Kg0 + (size_t)(tt) * BN * DK; \
        const __half* Vg_ = Vg0 + (tt) * BN; \
        uint32_t kd_ = smem_u32(&Ks[((bb) * BN + krow) * 72 + kq * 16]); \
        uint32_t vd_ = smem_u32(&Vs[((bb) * BN + krow) * 72 + kq * 16]); \
        cp16(kd_, Kg_);       cp16(kd_ + 16, Kg_ + 8); \
        cp16(vd_, Vg_);       cp16(vd_ + 16, Vg_ + 8); \
        cp4(smem_u32(&adjm[((bb) * QM + arow) * 2 + ahalf]), adjp_base + (size_t)(tt) * 2); \
        CP_COMMIT(); \
    } while (0)

    PREFETCH(0, 0);
    PREFETCH(1, 1);

    for (int tile = 0; tile < NT; tile++) {
        if (tile < NT - 1) { CP_WAIT(1); } else { CP_WAIT(0); }
        __syncthreads();    // tile data visible to all; all warps done with buffer (tile+2)%3
        if (tile + 2 < NT) PREFETCH(tile + 2, (tile + 2) % 3);

        const int buf = tile % 3;
        const __half* Kb = &Ks[buf * BN * 72];
        const __half* Vb = &Vs[buf * BN * 72];
        const uint32_t* ab = &adjm[buf * QM * 2];

        // ---- S = Q K^T ----
        float sacc[8][4] = {};
        #pragma unroll
        for (int nf = 0; nf < 8; nf++) {
            #pragma unroll
            for (int kc = 0; kc < 4; kc++) {
                uint32_t b0 = *(const uint32_t*)(&Kb[(nf * 8 + g) * 72 + kc * 16 + 2 * t]);
                uint32_t b1 = *(const uint32_t*)(&Kb[(nf * 8 + g) * 72 + kc * 16 + 2 * t + 8]);
                mma_f16(sacc[nf], qa[kc], b0, b1);
            }
        }

        // ---- masked online softmax ----
        uint32_t w0lo = ab[row0 * 2], w0hi = ab[row0 * 2 + 1];
        uint32_t w1lo = ab[row1 * 2], w1hi = ab[row1 * 2 + 1];
        float mx0 = -1e30f, mx1 = -1e30f;
        #pragma unroll
        for (int nf = 0; nf < 8; nf++) {
            int ca = nf * 8 + 2 * t, cb = ca + 1;
            uint32_t wr0 = (ca < 32) ? w0lo : w0hi;
            uint32_t wr1 = (ca < 32) ? w1lo : w1hi;
            int sa = ca & 31, sb = cb & 31;
            sacc[nf][0] = ((wr0 >> sa) & 1u) ? sacc[nf][0] : -1e38f;
            sacc[nf][1] = ((wr0 >> sb) & 1u) ? sacc[nf][1] : -1e38f;
            sacc[nf][2] = ((wr1 >> sa) & 1u) ? sacc[nf][2] : -1e38f;
            sacc[nf][3] = ((wr1 >> sb) & 1u) ? sacc[nf][3] : -1e38f;
            mx0 = fmaxf(mx0, fmaxf(sacc[nf][0], sacc[nf][1]));
            mx1 = fmaxf(mx1, fmaxf(sacc[nf][2], sacc[nf][3]));
        }
        mx0 = fmaxf(mx0, __shfl_xor_sync(0xffffffffu, mx0, 1));
        mx0 = fmaxf(mx0, __shfl_xor_sync(0xffffffffu, mx0, 2));
        mx1 = fmaxf(mx1, __shfl_xor_sync(0xffffffffu, mx1, 1));
        mx1 = fmaxf(mx1, __shfl_xor_sync(0xffffffffu, mx1, 2));
        float mn0 = fmaxf(m0r, mx0);
        float mn1 = fmaxf(m1r, mx1);
        float s0 = 0.f, s1 = 0.f;
        #pragma unroll
        for (int nf = 0; nf < 8; nf++) {
            float p0 = __expf(sacc[nf][0] - mn0);
            float p1 = __expf(sacc[nf][1] - mn0);
            float p2 = __expf(sacc[nf][2] - mn1);
            float p3 = __expf(sacc[nf][3] - mn1);
            s0 += p0 + p1;
            s1 += p2 + p3;
            sacc[nf][0] = p0; sacc[nf][1] = p1;
            sacc[nf][2] = p2; sacc[nf][3] = p3;
        }
        s0 += __shfl_xor_sync(0xffffffffu, s0, 1);
        s0 += __shfl_xor_sync(0xffffffffu, s0, 2);
        s1 += __shfl_xor_sync(0xffffffffu, s1, 1);
        s1 += __shfl_xor_sync(0xffffffffu, s1, 2);
        float cf0 = __expf(m0r - mn0);
        float cf1 = __expf(m1r - mn1);
        l0r = l0r * cf0 + s0;  m0r = mn0;
        l1r = l1r * cf1 + s1;  m1r = mn1;
        #pragma unroll
        for (int nf = 0; nf < 8; nf++) {
            oacc[nf][0] *= cf0; oacc[nf][1] *= cf0;
            oacc[nf][2] *= cf1; oacc[nf][3] *= cf1;
        }

        // ---- O += P V (no shuffles) ----
        #pragma unroll
        for (int kc = 0; kc < 4; kc++) {
            uint32_t pa[4];
            pa[0] = f22h(sacc[2 * kc][0],     sacc[2 * kc][1]);
            pa[1] = f22h(sacc[2 * kc][2],     sacc[2 * kc][3]);
            pa[2] = f22h(sacc[2 * kc + 1][0], sacc[2 * kc + 1][1]);
            pa[3] = f22h(sacc[2 * kc + 1][2], sacc[2 * kc + 1][3]);
            #pragma unroll
            for (int nf = 0; nf < 8; nf++) {
                uint32_t b0 = *(const uint32_t*)(&Vb[(nf * 8 + g) * 72 + kc * 16 + 2 * t]);
                uint32_t b1 = *(const uint32_t*)(&Vb[(nf * 8 + g) * 72 + kc * 16 + 2 * t + 8]);
                mma_f16(oacc[nf], pa, b0, b1);
            }
        }
    }
    #undef PREFETCH

    // ---- epilogue: write Hc as fp16 hi/lo planes ----
    const int h = bh & 3;
    float inv0 = (l0r > 0.f) ? 1.f / l0r : 0.f;
    float inv1 = (l1r > 0.f) ? 1.f / l1r : 0.f;
    const size_t o0 = (size_t)(b * NN + q0 + row0) * EE + h * DK;
    const size_t o1 = (size_t)(b * NN + q0 + row1) * EE + h * DK;
    #pragma unroll
    for (int nf = 0; nf < 8; nf++) {
        int c = nf * 8 + 2 * t;
        float a0 = oacc[nf][0] * inv0, a1 = oacc[nf][1] * inv0;
        float a2 = oacc[nf][2] * inv1, a3 = oacc[nf][3] * inv1;
        __half h0, l0, h1, l1, h2, l2, h3, l3;
        hilo_h(a0, h0, l0); hilo_h(a1, h1, l1);
        hilo_h(a2, h2, l2); hilo_h(a3, h3, l3);
        *(__half2*)(g_Hchi + o0 + c) = __halves2half2(h0, h1);
        *(__half2*)(g_Hclo + o0 + c) = __halves2half2(l0, l1);
        *(__half2*)(g_Hchi + o1 + c) = __halves2half2(h2, h3);
        *(__half2*)(g_Hclo + o1 + c) = __halves2half2(l2, l3);
    }
}

// ===========================================================================
// Kernel 3: out = Hc @ Wo^T + bo, raw-copy staging from pre-split planes.
// grid = (32, 4), 256 threads, 128-row tiles.
// ===========================================================================
__global__ void __launch_bounds__(256) out_mma_kernel(const float* __restrict__ bo,
                                                      float* __restrict__ out) {
    __shared__ __half Xhi[128][40], Xlo[128][40];
    __shared__ __half Whi[64][40], Wlo[64][40];   // [n][k]

    const int m0 = blockIdx.x * 128;
    const int c0 = blockIdx.y * 64;
    const int tid = threadIdx.x;
    const int wid = tid >> 5;
    const int lane = tid & 31;
    const int g = lane >> 2, t = lane & 3;
    const int row0 = wid * 16 + g, row1 = row0 + 8;

    const int xr = tid >> 1, xq = tid & 1;
    const __half* Xsrc_hi = g_Hchi + (size_t)(m0 + xr) * EE + xq * 16;
    const __half* Xsrc_lo = g_Hclo + (size_t)(m0 + xr) * EE + xq * 16;
    const int nr = tid >> 2, nq = tid & 3;
    const __half* Wsrc_hi = g_Wohi + (size_t)(c0 + nr) * EE + nq * 8;
    const __half* Wsrc_lo = g_Wolo + (size_t)(c0 + nr) * EE + nq * 8;

    float c[8][4] = {};

    for (int k0 = 0; k0 < EE; k0 += 32) {
        *(uint4*)(&Xhi[xr][xq * 16])     = *(const uint4*)(Xsrc_hi + k0);
        *(uint4*)(&Xhi[xr][xq * 16 + 8]) = *(const uint4*)(Xsrc_hi + k0 + 8);
        *(uint4*)(&Xlo[xr][xq * 16])     = *(const uint4*)(Xsrc_lo + k0);
        *(uint4*)(&Xlo[xr][xq * 16 + 8]) = *(const uint4*)(Xsrc_lo + k0 + 8);
        *(uint4*)(&Whi[nr][nq * 8])      = *(const uint4*)(Wsrc_hi + k0);
        *(uint4*)(&Wlo[nr][nq * 8])      = *(const uint4*)(Wsrc_lo + k0);
        __syncthreads();

        #pragma unroll
        for (int kc = 0; kc < 32; kc += 16) {
            uint32_t ahi[4], alo[4];
            ahi[0] = *(const uint32_t*)(&Xhi[row0][kc + 2 * t]);
            ahi[1] = *(const uint32_t*)(&Xhi[row1][kc + 2 * t]);
            ahi[2] = *(const uint32_t*)(&Xhi[row0][kc + 8 + 2 * t]);
            ahi[3] = *(const uint32_t*)(&Xhi[row1][kc + 8 + 2 * t]);
            alo[0] = *(const uint32_t*)(&Xlo[row0][kc + 2 * t]);
            alo[1] = *(const uint32_t*)(&Xlo[row1][kc + 2 * t]);
            alo[2] = *(const uint32_t*)(&Xlo[row0][kc + 8 + 2 * t]);
            alo[3] = *(const uint32_t*)(&Xlo[row1][kc + 8 + 2 * t]);
            #pragma unroll
            for (int nf = 0; nf < 8; nf++) {
                uint32_t bh0 = *(const uint32_t*)(&Whi[nf * 8 + g][kc + 2 * t]);
                uint32_t bh1 = *(const uint32_t*)(&Whi[nf * 8 + g][kc + 8 + 2 * t]);
                uint32_t bl0 = *(const uint32_t*)(&Wlo[nf * 8 + g][kc + 2 * t]);
                uint32_t bl1 = *(const uint32_t*)(&Wlo[nf * 8 + g][kc + 8 + 2 * t]);
                mma_f16(c[nf], ahi, bh0, bh1);
                mma_f16(c[nf], ahi, bl0, bl1);
                mma_f16(c[nf], alo, bh0, bh1);
            }
        }
        __syncthreads();
    }

    #pragma unroll
    for (int nf = 0; nf < 8; nf++) {
        int cc = c0 + nf * 8 + 2 * t;
        float b0v = bo[cc], b1v = bo[cc + 1];
        float2 w0 = {c[nf][0] + b0v, c[nf][1] + b1v};
        float2 w1 = {c[nf][2] + b0v, c[nf][3] + b1v};
        *(float2*)(out + (size_t)(m0 + row0) * EE + cc) = w0;
        *(float2*)(out + (size_t)(m0 + row1) * EE + cc) = w1;
    }
}

extern "C" void kernel_launch(void* const* d_in, const int* in_sizes, int n_in,
                              void* d_out, int out_size) {
    const float* x   = (const float*)d_in[0];
    const int*   adj = (const int*)  d_in[1];
    const float* Wq  = (const float*)d_in[2];
    const float* Wk  = (const float*)d_in[3];
    const float* Wv  = (const float*)d_in[4];
    const float* Wo  = (const float*)d_in[5];
    const float* bo  = (const float*)d_in[6];
    float* out = (float*)d_out;

    prep_split_kernel<<<(BB * NN * EE) / 256, 256>>>(x, Wq, Wk, Wv, Wo);
    pack_adj_kernel<<<(BB * NN * (NN / 32)) / (8 * 32), 256>>>(adj);
    qkv_mma_kernel<<<dim3((BB * NN) / 64, 12), 128>>>();

    cudaFuncSetAttribute(flash_mma_kernel,
                         cudaFuncAttributeMaxDynamicSharedMemorySize, FL_SMEM);
    flash_mma_kernel<<<dim3(NN / QM, BB * HH), 256, FL_SMEM>>>();

    out_mma_kernel<<<dim3((BB * NN) / 128, EE / 64), 256>>>(bo, out);
}